// round 1
// baseline (speedup 1.0000x reference)
#include <cuda_runtime.h>
#include <math_constants.h>

// Problem constants
#define BATCH     16
#define FRAMES    4000
#define BINS      257
#define HALF_N    256      // complex FFT size (512-pt real via 256-pt complex)
#define FRAME_LEN 512
#define HOP       128
#define G         16       // frames owned per block
#define NGROUPS   250      // FRAMES / G
#define FRAMES_SH (G + 3)  // computed frames per block (3 left-overlap)
#define OUT_LEN   512383   // (FRAMES-1)*HOP + FRAME_LEN - 1

__global__ __launch_bounds__(256, 4)
void istft_kernel(const float* __restrict__ xr,
                  const float* __restrict__ xi,
                  float* __restrict__ out)
{
    __shared__ float fr[FRAMES_SH * FRAME_LEN];   // 19*512 windowed frames
    __shared__ float wr[512], wi[512];            // 2-frame FFT workspace
    __shared__ float twc[256], tws[256];          // e^{+i*pi*t/256}
    __shared__ float effwin[512];

    const int tid   = threadIdx.x;                // 256 threads
    const int group = blockIdx.x;
    const int batch = blockIdx.y;
    const int f0     = group * G;
    const int fstart = f0 - 3;

    // --- one-time per-block tables ---
    {
        float s, c;
        sincosf(CUDART_PI_F * (float)tid * (1.0f / 256.0f), &s, &c);
        twc[tid] = c; tws[tid] = s;
    }
    for (int n = tid; n < 512; n += 256) {
        // periodic hann
        float w = 0.5f - 0.5f * cosf(2.0f * CUDART_PI_F * (float)n * (1.0f / 512.0f));
        int r = n & 127;
        float denom = 0.f;
        #pragma unroll
        for (int j = 0; j < 4; j++) {
            float wj = 0.5f - 0.5f * cosf(2.0f * CUDART_PI_F * (float)(r + 128 * j) * (1.0f / 512.0f));
            denom += wj * wj;
        }
        // fold irfft 1/512 scale (and the Xe/Xo half-factors) into window
        effwin[n] = w / (denom * 512.0f);
    }
    const int lf_start = (group == 0) ? 3 : 0;
    if (group == 0) {
        for (int i = tid; i < 3 * FRAME_LEN; i += 256) fr[i] = 0.f;
    }
    __syncthreads();

    // --- compute windowed irfft frames, 2 per iteration ---
    const int nFr    = FRAMES_SH - lf_start;
    const int nPairs = (nFr + 1) >> 1;
    const int slot   = tid >> 7;       // which of the 2 concurrent frames
    const int tt     = tid & 127;
    const int base   = slot << 8;      // slot * 256

    for (int p = 0; p < nPairs; ++p) {
        const int lf = lf_start + 2 * p + slot;
        const bool active = (lf < FRAMES_SH);
        const int f = fstart + lf;

        if (active) {
            const float* pre = xr + ((size_t)batch * FRAMES + f) * BINS;
            const float* pim = xi + ((size_t)batch * FRAMES + f) * BINS;
            #pragma unroll
            for (int kk = 0; kk < 2; kk++) {
                int k  = tt + (kk << 7);        // 0..255
                int km = 256 - k;               // 1..256
                // a = X[k], b = conj(X[256-k]); imag of bins 0/256 is irrelevant
                float ar = pre[k];
                float ai = (k == 0) ? 0.f : pim[k];
                float br = pre[km];
                float bi = (km == 256) ? 0.f : -pim[km];
                float er = ar + br, ei = ai + bi;   // 2*Xe
                float dr = ar - br, di = ai - bi;   // 2*Xo before rotation
                float c = twc[k], s = tws[k];       // e^{+2*pi*i*k/512}
                float xo_r = dr * c - di * s;
                float xo_i = dr * s + di * c;
                // Z = Xe + i*Xo, store bit-reversed for DIT
                int dst = base + (int)(__brev((unsigned)k) >> 24);
                wr[dst] = er - xo_i;
                wi[dst] = ei + xo_r;
            }
        }
        __syncthreads();

        // 8 radix-2 DIT stages, inverse sign (+), twiddle e^{+2*pi*i*j/m}
        #pragma unroll
        for (int st = 1; st <= 8; ++st) {
            const int half = 1 << (st - 1);
            if (active) {
                int j  = tt & (half - 1);
                int g  = tt >> (st - 1);
                int i0 = base + (g << st) + j;
                int i1 = i0 + half;
                int ti = j << (9 - st);             // j * (512/m)
                float c = twc[ti], s = tws[ti];
                float vr = wr[i1] * c - wi[i1] * s;
                float vi = wr[i1] * s + wi[i1] * c;
                float ur = wr[i0], ui = wi[i0];
                wr[i0] = ur + vr; wi[i0] = ui + vi;
                wr[i1] = ur - vr; wi[i1] = ui - vi;
            }
            __syncthreads();
        }

        // z[n] = x[2n] + i*x[2n+1]; apply synthesis window
        if (active) {
            float* dstf = fr + lf * FRAME_LEN;
            #pragma unroll
            for (int kk = 0; kk < 2; kk++) {
                int n2 = tt + (kk << 7);
                float zr = wr[base + n2], zi = wi[base + n2];
                dstf[2 * n2]     = zr * effwin[2 * n2];
                dstf[2 * n2 + 1] = zi * effwin[2 * n2 + 1];
            }
        }
        __syncthreads();   // workspace reused next pair
    }

    // --- gather overlap-add for the samples this block owns ---
    const int owned = (group == NGROUPS - 1) ? (G * HOP + 384) : (G * HOP);
    const int sbase = f0 * HOP;
    float* outb = out + (size_t)batch * OUT_LEN;
    for (int s = tid; s < owned; s += 256) {
        int q = s >> 7, r = s & 127;
        float acc = 0.f;
        #pragma unroll
        for (int d = 0; d < 4; d++) {
            int lf = q - d + 3;                      // frame slot covering s
            if (lf < FRAMES_SH)
                acc += fr[lf * FRAME_LEN + r + (d << 7)];
        }
        int S = sbase + s;
        if (S < OUT_LEN) outb[S] = acc;              // drop final sample
    }
}

extern "C" void kernel_launch(void* const* d_in, const int* in_sizes, int n_in,
                              void* d_out, int out_size)
{
    const float* stft_real = (const float*)d_in[0];
    const float* stft_imag = (const float*)d_in[1];
    float* out = (float*)d_out;
    (void)in_sizes; (void)n_in; (void)out_size;

    dim3 grid(NGROUPS, BATCH);
    istft_kernel<<<grid, 256>>>(stft_real, stft_imag, out);
}

// round 2
// speedup vs baseline: 1.7073x; 1.7073x over previous
#include <cuda_runtime.h>
#include <math_constants.h>

#define BATCH     16
#define FRAMES    4000
#define BINS      257
#define FRAME_LEN 512
#define HOP       128
#define G         16
#define NGROUPS   250
#define FRAMES_SH (G + 3)
#define OUT_LEN   512383

// advance (c,s) by constant rotation (ic,is)
__device__ __forceinline__ void cstep(float& c, float& s, float ic, float is_) {
    float nc = c * ic - s * is_;
    s = c * is_ + s * ic;
    c = nc;
}

__global__ __launch_bounds__(256, 2)
void istft_kernel(const float* __restrict__ xr,
                  const float* __restrict__ xi,
                  float* __restrict__ out)
{
    __shared__ __align__(16) float fr[FRAMES_SH * FRAME_LEN];  // windowed frames
    __shared__ __align__(8)  float effwin[FRAME_LEN];

    const int tid   = threadIdx.x;     // 256
    const int warp  = tid >> 5;
    const int lane  = tid & 31;
    const int group = blockIdx.x;
    const int batch = blockIdx.y;
    const int f0     = group * G;
    const int fstart = f0 - 3;

    // ---- effective synthesis window (hann / OLA(hann^2), 1/512 folded in) ----
    for (int n = tid; n < FRAME_LEN; n += 256) {
        float w = 0.5f - 0.5f * cosf(2.0f * CUDART_PI_F * (float)n * (1.0f / 512.0f));
        int r = n & 127;
        float denom = 0.f;
        #pragma unroll
        for (int q = 0; q < 4; q++) {
            float wq = 0.5f - 0.5f * cosf(2.0f * CUDART_PI_F * (float)(r + 128 * q) * (1.0f / 512.0f));
            denom += wq * wq;
        }
        effwin[n] = w / (denom * 512.0f);
    }
    if (group == 0)
        for (int i = tid; i < 3 * FRAME_LEN; i += 256) fr[i] = 0.f;
    __syncthreads();

    // ---- per-lane twiddle bases (frame-invariant) ----
    float pbs, pbc;   __sincosf(CUDART_PI_F * (float)lane        * (1.0f / 32.0f), &pbs,  &pbc);   // prerot: pi*k0/256, k0=8*lane
    float b128s, b128c; __sincosf(CUDART_PI_F * (float)(lane & 15) * (1.0f / 16.0f), &b128s, &b128c);
    float b64s,  b64c;  __sincosf(CUDART_PI_F * (float)(lane & 7)  * (1.0f / 8.0f),  &b64s,  &b64c);
    float b32s,  b32c;  __sincosf(CUDART_PI_F * (float)(lane & 3)  * (1.0f / 4.0f),  &b32s,  &b32c);

    const int k0 = lane * 8;
    const int rl = (int)(__brev((unsigned)lane) >> 27);   // rev5(lane)

    // ---- frames: one warp per frame ----
    for (int rr = 0; rr < 3; rr++) {
        const int lf = warp + 8 * rr;
        if (lf >= FRAMES_SH) break;
        if (group == 0 && lf < 3) continue;
        const int f = fstart + lf;

        const float* pre = xr + ((size_t)batch * FRAMES + f) * BINS;
        const float* pim = xi + ((size_t)batch * FRAMES + f) * BINS;

        float zr[8], zi[8];

        // Hermitian pack + pre-rotation: Z[k], k = 8*lane + j (natural order)
        {
            float pc = pbc, ps = pbs;
            #pragma unroll
            for (int j = 0; j < 8; j++) {
                int k  = k0 + j;
                int km = 256 - k;
                float ar = pre[k];
                float ai = (k == 0) ? 0.f : pim[k];
                float br = pre[km];
                float bi = (km == 256) ? 0.f : -pim[km];
                float er = ar + br, ei = ai + bi;
                float dr = ar - br, di = ai - bi;
                float xo_r = dr * pc - di * ps;
                float xo_i = dr * ps + di * pc;
                zr[j] = er - xo_i;
                zi[j] = ei + xo_r;
                cstep(pc, ps, 0.99992470183914454f, 0.012271538285719925f); // e^{i*pi/256}
            }
        }

        // ---- DIF inverse FFT-256, natural in -> bit-reversed out ----
        // lane-dim stage macro: distance d = 8*MASK
        #define LANE_STAGE(MASK, BC, BS, IC, ISV)                              \
        {                                                                      \
            const bool hi = (lane & (MASK)) != 0;                              \
            float tc = (BC), ts = (BS);                                        \
            _Pragma("unroll")                                                  \
            for (int j = 0; j < 8; j++) {                                      \
                float orr = __shfl_xor_sync(0xffffffffu, zr[j], (MASK));       \
                float oii = __shfl_xor_sync(0xffffffffu, zi[j], (MASK));       \
                if (hi) {                                                      \
                    float tr = orr - zr[j], ti = oii - zi[j];                  \
                    zr[j] = tr * tc - ti * ts;                                 \
                    zi[j] = tr * ts + ti * tc;                                 \
                } else {                                                       \
                    zr[j] += orr; zi[j] += oii;                                \
                }                                                              \
                cstep(tc, ts, (IC), (ISV));                                    \
            }                                                                  \
        }

        LANE_STAGE(16, b128c, b128s, 0.99969881869620425f, 0.024541228522912288f) // d=128
        LANE_STAGE(8,  b64c,  b64s,  0.99879545620517241f, 0.049067674327418015f) // d=64
        LANE_STAGE(4,  b32c,  b32s,  0.99518472667219693f, 0.098017140329560604f) // d=32
        #undef LANE_STAGE

        // d=16 (mask 2): tw = (lane&1 ? i : 1) * e^{i*pi*j/16}  (constants)
        {
            const float C16[8] = {1.f, 0.98078528040323044f, 0.92387953251128674f, 0.83146961230254524f,
                                  0.70710678118654752f, 0.55557023301960222f, 0.38268343236508977f, 0.19509032201612827f};
            const float S16[8] = {0.f, 0.19509032201612827f, 0.38268343236508977f, 0.55557023301960222f,
                                  0.70710678118654752f, 0.83146961230254524f, 0.92387953251128674f, 0.98078528040323044f};
            const bool hi  = (lane & 2) != 0;
            const bool rot = (lane & 1) != 0;
            #pragma unroll
            for (int j = 0; j < 8; j++) {
                float c = rot ? -S16[j] : C16[j];
                float s = rot ?  C16[j] : S16[j];
                float orr = __shfl_xor_sync(0xffffffffu, zr[j], 2);
                float oii = __shfl_xor_sync(0xffffffffu, zi[j], 2);
                if (hi) {
                    float tr = orr - zr[j], ti = oii - zi[j];
                    zr[j] = tr * c - ti * s;
                    zi[j] = tr * s + ti * c;
                } else { zr[j] += orr; zi[j] += oii; }
            }
        }

        // d=8 (mask 1): tw = e^{i*pi*j/8}  (constants)
        {
            const float C8[8] = {1.f, 0.92387953251128674f, 0.70710678118654752f, 0.38268343236508977f,
                                 0.f, -0.38268343236508977f, -0.70710678118654752f, -0.92387953251128674f};
            const float S8[8] = {0.f, 0.38268343236508977f, 0.70710678118654752f, 0.92387953251128674f,
                                 1.f, 0.92387953251128674f, 0.70710678118654752f, 0.38268343236508977f};
            const bool hi = (lane & 1) != 0;
            #pragma unroll
            for (int j = 0; j < 8; j++) {
                float orr = __shfl_xor_sync(0xffffffffu, zr[j], 1);
                float oii = __shfl_xor_sync(0xffffffffu, zi[j], 1);
                if (hi) {
                    float tr = orr - zr[j], ti = oii - zi[j];
                    zr[j] = tr * C8[j] - ti * S8[j];
                    zi[j] = tr * S8[j] + ti * C8[j];
                } else { zr[j] += orr; zi[j] += oii; }
            }
        }

        // in-register stages
        #define RB(A,B,C,S)  { float tr=zr[A]-zr[B], ti=zi[A]-zi[B]; zr[A]+=zr[B]; zi[A]+=zi[B]; \
                               zr[B]=tr*(C)-ti*(S); zi[B]=tr*(S)+ti*(C); }
        #define RB1(A,B)     { float tr=zr[A]-zr[B], ti=zi[A]-zi[B]; zr[A]+=zr[B]; zi[A]+=zi[B]; \
                               zr[B]=tr; zi[B]=ti; }
        #define RBI(A,B)     { float tr=zr[A]-zr[B], ti=zi[A]-zi[B]; zr[A]+=zr[B]; zi[A]+=zi[B]; \
                               zr[B]=-ti; zi[B]=tr; }
        const float R2 = 0.70710678118654752f;
        // d=4: tw_j = e^{i*pi*j/4}, j=0..3
        RB1(0,4); RB(1,5,R2,R2); RBI(2,6); RB(3,7,-R2,R2);
        // d=2: tw = 1, i
        RB1(0,2); RBI(1,3); RB1(4,6); RBI(5,7);
        // d=1: tw = 1
        RB1(0,1); RB1(2,3); RB1(4,5); RB1(6,7);
        #undef RB
        #undef RB1
        #undef RBI

        // ---- windowed store: pos (lane,j) holds z[rev3(j)*32 + rev5(lane)] ----
        {
            float2* frow = reinterpret_cast<float2*>(fr) + lf * 256;
            const float2* ew = reinterpret_cast<const float2*>(effwin);
            const int rev3[8] = {0, 4, 2, 6, 1, 5, 3, 7};
            #pragma unroll
            for (int j = 0; j < 8; j++) {
                int m = rev3[j] * 32 + rl;          // z index; x[2m], x[2m+1]
                float2 w2 = ew[m];
                frow[m] = make_float2(zr[j] * w2.x, zi[j] * w2.y);
            }
        }
    }
    __syncthreads();

    // ---- gather overlap-add for owned output range ----
    const int owned = (group == NGROUPS - 1) ? (G * HOP + 384) : (G * HOP);
    const int sbase = f0 * HOP;
    float* outb = out + (size_t)batch * OUT_LEN;
    for (int s = tid; s < owned; s += 256) {
        int q = s >> 7, r = s & 127;
        float acc = 0.f;
        #pragma unroll
        for (int d = 0; d < 4; d++) {
            int lf = q - d + 3;
            if (lf < FRAMES_SH)
                acc += fr[lf * FRAME_LEN + r + (d << 7)];
        }
        int S = sbase + s;
        if (S < OUT_LEN) outb[S] = acc;
    }
}

extern "C" void kernel_launch(void* const* d_in, const int* in_sizes, int n_in,
                              void* d_out, int out_size)
{
    const float* stft_real = (const float*)d_in[0];
    const float* stft_imag = (const float*)d_in[1];
    float* out = (float*)d_out;
    (void)in_sizes; (void)n_in; (void)out_size;

    dim3 grid(NGROUPS, BATCH);
    istft_kernel<<<grid, 256>>>(stft_real, stft_imag, out);
}

// round 3
// speedup vs baseline: 3.3931x; 1.9874x over previous
#include <cuda_runtime.h>
#include <math_constants.h>

#define BATCH     16
#define FRAMES    4000
#define BINS      257
#define FRAME_LEN 512
#define HOP       128
#define G         20
#define NGROUPS   200
#define FRAMES_SH (G + 3)
#define OUT_LEN   512383

__global__ __launch_bounds__(256, 3)
void istft_kernel(const float* __restrict__ xr,
                  const float* __restrict__ xi,
                  float* __restrict__ out)
{
    __shared__ __align__(16) float fr[FRAMES_SH * FRAME_LEN];  // swizzled windowed frames
    __shared__ __align__(16) float effwin[FRAME_LEN];          // swizzled window

    const int tid   = threadIdx.x;     // 256
    const int warp  = tid >> 5;
    const int lane  = tid & 31;
    const int group = blockIdx.x;
    const int batch = blockIdx.y;
    const int f0     = group * G;
    const int fstart = f0 - 3;

    // effective window: hann / (OLA(hann^2)=1.5) / 512  (stored swizzled)
    for (int n = tid; n < FRAME_LEN; n += 256) {
        float w = 0.5f - 0.5f * cosf(2.0f * CUDART_PI_F * (float)n * (1.0f / 512.0f));
        int i4 = n >> 2;
        int p  = ((i4 ^ ((i4 >> 3) & 7)) << 2) | (n & 3);
        effwin[p] = w * (1.0f / 768.0f);
    }
    if (group == 0)
        for (int i = tid; i < 3 * FRAME_LEN; i += 256) fr[i] = 0.f;
    __syncthreads();

    // ---- per-lane twiddles (frame-invariant, all constants) ----
    float pbs, pbc;  __sincosf(CUDART_PI_F * (float)lane * (1.0f / 256.0f), &pbs, &pbc);
    float s128, c128; __sincosf(CUDART_PI_F * (float)lane * (1.0f / 128.0f), &s128, &c128);
    float s64,  c64;  __sincosf(CUDART_PI_F * (float)lane * (1.0f / 64.0f),  &s64,  &c64);
    float s32,  c32;  __sincosf(CUDART_PI_F * (float)lane * (1.0f / 32.0f),  &s32,  &c32);
    float s16,  c16;  __sincosf(CUDART_PI_F * (float)(lane & 15) * (1.0f / 16.0f), &s16, &c16);
    float s8t,  c8t;  __sincosf(CUDART_PI_F * (float)(lane & 7)  * (1.0f / 8.0f),  &s8t, &c8t);
    float s4t,  c4t;  __sincosf(CUDART_PI_F * (float)(lane & 3)  * (1.0f / 4.0f),  &s4t, &c4t);

    const float R2 = 0.70710678118654752f;
    // w128[j] = e^{i*pi*lane/128} * e^{i*pi*j/4}, j=0..3
    float w128c[4], w128s[4];
    w128c[0] = c128;              w128s[0] = s128;
    w128c[1] = R2 * (c128 - s128); w128s[1] = R2 * (c128 + s128);
    w128c[2] = -s128;             w128s[2] = c128;
    w128c[3] = -R2 * (c128 + s128); w128s[3] = R2 * (c128 - s128);

    const int rl = (int)(__brev((unsigned)lane) >> 27);  // rev5(lane)

    // prerot per-register constants e^{i*pi*j/8}
    const float C8[8] = {1.f, 0.92387953251128674f, 0.70710678118654752f, 0.38268343236508977f,
                         0.f, -0.38268343236508977f, -0.70710678118654752f, -0.92387953251128674f};
    const float S8[8] = {0.f, 0.38268343236508977f, 0.70710678118654752f, 0.92387953251128674f,
                         1.f, 0.92387953251128674f, 0.70710678118654752f, 0.38268343236508977f};

    for (int rr = 0; rr < 3; rr++) {
        const int lf = warp + 8 * rr;
        if (lf >= FRAMES_SH) break;
        if (group == 0 && lf < 3) continue;
        const int f = fstart + lf;

        const float* pre = xr + ((size_t)batch * FRAMES + f) * BINS;
        const float* pim = xi + ((size_t)batch * FRAMES + f) * BINS;

        float zr[8], zi[8];

        // Hermitian pack + pre-rotation, k = 32*j + lane (coalesced loads)
        #pragma unroll
        for (int j = 0; j < 8; j++) {
            int k  = 32 * j + lane;
            int km = 256 - k;
            float ar = pre[k];
            float br = pre[km];
            float ai, bi;
            if (k == 0) { ai = 0.f; bi = 0.f; }
            else        { ai = pim[k]; bi = -pim[km]; }
            float er = ar + br, ei = ai + bi;
            float dr = ar - br, di = ai - bi;
            float pc = pbc * C8[j] - pbs * S8[j];
            float ps = pbc * S8[j] + pbs * C8[j];
            float xo_r = dr * pc - di * ps;
            float xo_i = dr * ps + di * pc;
            zr[j] = er - xo_i;
            zi[j] = ei + xo_r;
        }

        // ---- DIF inverse FFT-256 (sign +i), natural in -> bit-reversed out ----
        // register stage h=128: pairs (j, j+4)
        #pragma unroll
        for (int j = 0; j < 4; j++) {
            float tr = zr[j] - zr[j + 4], ti = zi[j] - zi[j + 4];
            zr[j] += zr[j + 4]; zi[j] += zi[j + 4];
            zr[j + 4] = tr * w128c[j] - ti * w128s[j];
            zi[j + 4] = tr * w128s[j] + ti * w128c[j];
        }
        // register stage h=64: (0,2),(4,6) tw=t64 ; (1,3),(5,7) tw=i*t64
        #define RB64(A,B,CC,SS) { float tr=zr[A]-zr[B], ti=zi[A]-zi[B]; \
            zr[A]+=zr[B]; zi[A]+=zi[B]; zr[B]=tr*(CC)-ti*(SS); zi[B]=tr*(SS)+ti*(CC); }
        RB64(0, 2, c64, s64)  RB64(4, 6, c64, s64)
        RB64(1, 3, -s64, c64) RB64(5, 7, -s64, c64)
        // register stage h=32: (0,1),(2,3),(4,5),(6,7) tw=t32
        RB64(0, 1, c32, s32) RB64(2, 3, c32, s32)
        RB64(4, 5, c32, s32) RB64(6, 7, c32, s32)
        #undef RB64

        // lane stages: masks 16, 8, 4 with per-lane twiddles
        #define LSTAGE(MASK, TC, TS)                                           \
        {                                                                      \
            const bool hi = (lane & (MASK)) != 0;                              \
            _Pragma("unroll")                                                  \
            for (int j = 0; j < 8; j++) {                                      \
                float orr = __shfl_xor_sync(0xffffffffu, zr[j], (MASK));       \
                float oii = __shfl_xor_sync(0xffffffffu, zi[j], (MASK));       \
                if (hi) {                                                      \
                    float tr = orr - zr[j], ti = oii - zi[j];                  \
                    zr[j] = tr * (TC) - ti * (TS);                             \
                    zi[j] = tr * (TS) + ti * (TC);                             \
                } else { zr[j] += orr; zi[j] += oii; }                         \
            }                                                                  \
        }
        LSTAGE(16, c16, s16)
        LSTAGE(8,  c8t, s8t)
        LSTAGE(4,  c4t, s4t)
        #undef LSTAGE

        // mask 2: tw = (lane&1) ? i : 1
        {
            const bool hi  = (lane & 2) != 0;
            const bool rot = (lane & 1) != 0;
            #pragma unroll
            for (int j = 0; j < 8; j++) {
                float orr = __shfl_xor_sync(0xffffffffu, zr[j], 2);
                float oii = __shfl_xor_sync(0xffffffffu, zi[j], 2);
                if (hi) {
                    float tr = orr - zr[j], ti = oii - zi[j];
                    if (rot) { zr[j] = -ti; zi[j] = tr; }
                    else     { zr[j] = tr;  zi[j] = ti; }
                } else { zr[j] += orr; zi[j] += oii; }
            }
        }
        // mask 1: tw = 1
        {
            const bool hi = (lane & 1) != 0;
            #pragma unroll
            for (int j = 0; j < 8; j++) {
                float orr = __shfl_xor_sync(0xffffffffu, zr[j], 1);
                float oii = __shfl_xor_sync(0xffffffffu, zi[j], 1);
                if (hi) { zr[j] = orr - zr[j]; zi[j] = oii - zi[j]; }
                else    { zr[j] += orr;        zi[j] += oii; }
            }
        }

        // ---- unscramble: lane L, slot t <- z[8L + t] (from lane rev5(L), reg rev3(t)) ----
        float nr[8], ni[8];
        {
            const int rev3t[8] = {0, 4, 2, 6, 1, 5, 3, 7};
            #pragma unroll
            for (int t = 0; t < 8; t++) {
                nr[t] = __shfl_sync(0xffffffffu, zr[rev3t[t]], rl);
                ni[t] = __shfl_sync(0xffffffffu, zi[rev3t[t]], rl);
            }
        }

        // ---- windowed float4 stores, XOR-swizzled (conflict-free) ----
        {
            float4* frow4 = reinterpret_cast<float4*>(fr + lf * FRAME_LEN);
            const float4* ew4 = reinterpret_cast<const float4*>(effwin);
            #pragma unroll
            for (int q = 0; q < 4; q++) {
                int i4 = 4 * lane + q;
                int p4 = i4 ^ ((i4 >> 3) & 7);
                float4 w4 = ew4[p4];
                frow4[p4] = make_float4(nr[2 * q]     * w4.x,
                                        ni[2 * q]     * w4.y,
                                        nr[2 * q + 1] * w4.z,
                                        ni[2 * q + 1] * w4.w);
            }
        }
    }
    __syncthreads();

    // ---- gather overlap-add (swizzle-aware reads, coalesced) ----
    const int owned = (group == NGROUPS - 1) ? (G * HOP + 384) : (G * HOP);
    const int sbase = f0 * HOP;
    float* outb = out + (size_t)batch * OUT_LEN;
    for (int s = tid; s < owned; s += 256) {
        int qf = s >> 7, r = s & 127;
        float acc = 0.f;
        #pragma unroll
        for (int d = 0; d < 4; d++) {
            int lf = qf - d + 3;
            if (lf < FRAMES_SH) {
                int n  = r + (d << 7);
                int i4 = n >> 2;
                int pf = ((i4 ^ ((i4 >> 3) & 7)) << 2) | (n & 3);
                acc += fr[lf * FRAME_LEN + pf];
            }
        }
        int S = sbase + s;
        if (S < OUT_LEN) outb[S] = acc;
    }
}

extern "C" void kernel_launch(void* const* d_in, const int* in_sizes, int n_in,
                              void* d_out, int out_size)
{
    const float* stft_real = (const float*)d_in[0];
    const float* stft_imag = (const float*)d_in[1];
    float* out = (float*)d_out;
    (void)in_sizes; (void)n_in; (void)out_size;

    dim3 grid(NGROUPS, BATCH);
    istft_kernel<<<grid, 256>>>(stft_real, stft_imag, out);
}